// round 8
// baseline (speedup 1.0000x reference)
#include <cuda_runtime.h>
#include <cuda_bf16.h>

// VoConstruction: out[b] = O @ (Umat d Umat^H), O = [[0,1],[1,0]].
// Closed form (delta factor cancels in U d U^H):
//   c = cos(u1), s = sin(u1), lam1 = 2*x1, lam2 = 2*x2*(1-|x1|)
//   H00 = lam1 c^2 + lam2 s^2   H11 = lam1 s^2 + lam2 c^2    (real)
//   H01 = c s (lam2 - lam1) e^{i 2 u0},  H10 = conj(H01)
// O swaps rows: row0 = [H10, H11], row1 = [H00, H01].
//
// Harness dtype contract has no complex64 -> output is float32 (real part):
//   out[b] = [[Re H10, Re H11],[Re H00, Re H01]] = (wc, h11, h00, wc), 4 floats.
// A runtime branch also supports interleaved-complex layout (8 floats/elem)
// in case out_size indicates it. Writes are clamped to out_size floats either
// way, so no layout hypothesis can overrun d_out.

__global__ __launch_bounds__(256)
void vo_real_kernel(const float* __restrict__ U,    // [B,3]
                    const float* __restrict__ X1,   // [B]
                    const float* __restrict__ X2,   // [B]
                    float4* __restrict__ out,       // [B,2,2] f32 -> 1 float4/elem
                    int B)
{
    int i = blockIdx.x * blockDim.x + threadIdx.x;
    if (i >= B) return;

    float u0 = U[3 * i + 0];
    float th = U[3 * i + 1];
    float l1 = X1[i];
    float l2 = X2[i];

    float s, ct;
    __sincosf(th, &s, &ct);
    float c2 = __cosf(2.0f * u0);          // only the real part survives

    float lam1 = 2.0f * l1;
    float lam2 = 2.0f * l2 * (1.0f - fabsf(l1));

    float cc = ct * ct;
    float ss = s * s;
    float h00 = fmaf(lam1, cc, lam2 * ss);
    float h11 = fmaf(lam1, ss, lam2 * cc);
    float wc  = ct * s * (lam2 - lam1) * c2;   // Re H01 = Re H10

    out[i] = make_float4(wc, h11, h00, wc);    // [ReH10, ReH11, ReH00, ReH01]
}

__global__ __launch_bounds__(256)
void vo_cplx_kernel(const float* __restrict__ U,
                    const float* __restrict__ X1,
                    const float* __restrict__ X2,
                    float4* __restrict__ out,      // 2 float4 per element
                    int B)
{
    int i = blockIdx.x * blockDim.x + threadIdx.x;
    if (i >= B) return;

    float u0 = U[3 * i + 0];
    float th = U[3 * i + 1];
    float l1 = X1[i];
    float l2 = X2[i];

    float s, ct;
    __sincosf(th, &s, &ct);
    float s2, c2;
    __sincosf(2.0f * u0, &s2, &c2);

    float lam1 = 2.0f * l1;
    float lam2 = 2.0f * l2 * (1.0f - fabsf(l1));

    float cc = ct * ct;
    float ss = s * s;
    float h00 = fmaf(lam1, cc, lam2 * ss);
    float h11 = fmaf(lam1, ss, lam2 * cc);
    float w   = ct * s * (lam2 - lam1);
    float wc  = w * c2;
    float ws  = w * s2;

    float4* o = out + (size_t)2 * i;
    o[0] = make_float4(wc, -ws, h11, 0.0f);   // row0: H10, H11
    o[1] = make_float4(h00, 0.0f, wc, ws);    // row1: H00, H01
}

extern "C" void kernel_launch(void* const* d_in, const int* in_sizes, int n_in,
                              void* d_out, int out_size)
{
    if (n_in < 3) return;

    // U = largest input; x1, x2 = the two largest remaining (original order).
    int iU = 0;
    for (int i = 1; i < n_in; ++i)
        if (in_sizes[i] > in_sizes[iU]) iU = i;

    int iA = -1, iB = -1;
    for (int i = 0; i < n_in; ++i) {
        if (i == iU) continue;
        if (iA < 0) { iA = i; continue; }
        if (iB < 0) { iB = i; continue; }
        int iMin = (in_sizes[iA] <= in_sizes[iB]) ? iA : iB;
        if (in_sizes[i] > in_sizes[iMin]) {
            if (iMin == iA) iA = iB;
            iB = i;
        }
    }
    if (iA < 0 || iB < 0) return;
    int iX1 = (iA < iB) ? iA : iB;
    int iX2 = (iA < iB) ? iB : iA;

    // B from input element counts (documented contract for float32 buffers).
    long long B = in_sizes[iX1];
    if ((long long)in_sizes[iX2] < B) B = in_sizes[iX2];
    if ((long long)in_sizes[iU] / 3 < B) B = in_sizes[iU] / 3;
    if (B <= 0) return;

    const float* pU  = (const float*)d_in[iU];
    const float* pX1 = (const float*)d_in[iX1];
    const float* pX2 = (const float*)d_in[iX2];

    dim3 block(256);

    if ((long long)out_size >= 8 * B) {
        // interleaved complex64 layout: 8 floats per element
        long long Bc = B;
        if ((long long)out_size / 8 < Bc) Bc = out_size / 8;
        int Bi = (int)Bc;
        dim3 grid((Bi + 255) / 256);
        vo_cplx_kernel<<<grid, block>>>(pU, pX1, pX2, (float4*)d_out, Bi);
    } else {
        // float32 real-part layout: 4 floats per element (expected path)
        long long Br = B;
        if ((long long)out_size / 4 < Br) Br = out_size / 4;
        int Bi = (int)Br;
        dim3 grid((Bi + 255) / 256);
        vo_real_kernel<<<grid, block>>>(pU, pX1, pX2, (float4*)d_out, Bi);
    }
}